// round 12
// baseline (speedup 1.0000x reference)
#include <cuda_runtime.h>
#include <cuda_bf16.h>
#include <cstddef>

#define B_ROWS 4096
#define D_INF  128
#define H_DIM  512
#define D_OUT  256
#define M_CON  64

#define OMEGA_F 1.7f

typedef unsigned long long u64;
typedef unsigned int u32;

// ---------------- f32x2 helpers (trunk GEMM) ----------------
__device__ __forceinline__ u64 ffma2(u64 a, u64 b, u64 c) {
    u64 d; asm("fma.rn.f32x2 %0,%1,%2,%3;" : "=l"(d) : "l"(a), "l"(b), "l"(c)); return d;
}
__device__ __forceinline__ u64 pack2(float x, float y) {
    u64 d; asm("mov.b64 %0,{%1,%2};" : "=l"(d) : "f"(x), "f"(y)); return d;
}
__device__ __forceinline__ void unpack2(u64 v, float& x, float& y) {
    asm("mov.b64 {%0,%1},%2;" : "=f"(x), "=f"(y) : "l"(v));
}

// ---------------- bf16 split helpers ----------------
__device__ __forceinline__ u32 pack_bf16(float lo, float hi) {
    u32 d; asm("cvt.rn.bf16x2.f32 %0, %1, %2;" : "=r"(d) : "f"(hi), "f"(lo)); return d;
}
__device__ __forceinline__ float bflo(u32 p) { return __uint_as_float(p << 16); }
__device__ __forceinline__ float bfhi(u32 p) { return __uint_as_float(p & 0xffff0000u); }
__device__ __forceinline__ void split2(float v0, float v1, u32& hp, u32& lp) {
    hp = pack_bf16(v0, v1);
    lp = pack_bf16(v0 - bflo(hp), v1 - bfhi(hp));
}

// ---------------- mma / ldmatrix ----------------
__device__ __forceinline__ void mma_bf16(float* c, const u32* a, const u32* b) {
    asm volatile(
        "mma.sync.aligned.m16n8k16.row.col.f32.bf16.bf16.f32 "
        "{%0,%1,%2,%3},{%4,%5,%6,%7},{%8,%9},{%0,%1,%2,%3};"
        : "+f"(c[0]), "+f"(c[1]), "+f"(c[2]), "+f"(c[3])
        : "r"(a[0]), "r"(a[1]), "r"(a[2]), "r"(a[3]), "r"(b[0]), "r"(b[1]));
}
__device__ __forceinline__ void ldsm4(u32* r, u32 addr) {
    asm volatile("ldmatrix.sync.aligned.m8n8.x4.shared.b16 {%0,%1,%2,%3}, [%4];"
        : "=r"(r[0]), "=r"(r[1]), "=r"(r[2]), "=r"(r[3]) : "r"(addr));
}
__device__ __forceinline__ void ldsm2(u32* r, u32 addr) {
    asm volatile("ldmatrix.sync.aligned.m8n8.x2.shared.b16 {%0,%1}, [%2];"
        : "=r"(r[0]), "=r"(r[1]) : "r"(addr));
}

__device__ float g_Mop[M_CON * D_OUT];
__device__ float g_h1[B_ROWS * H_DIM];
__device__ float g_h2[B_ROWS * H_DIM];
__device__ float g_y0[B_ROWS * D_OUT];

// ---------------------------------------------------------------------------
// Setup: Mop = inv(A A^T) @ A.   Single CTA, 256 threads.
// ---------------------------------------------------------------------------
__global__ void __launch_bounds__(256) setup_kernel(const float* __restrict__ A,
                                                    float* __restrict__ Mop) {
    __shared__ float Gs[64][65];
    __shared__ float Ks[64][65];
    __shared__ float fcol[64];
    int tid = threadIdx.x;

    for (int idx = tid; idx < 64 * 64; idx += 256) {
        int i = idx >> 6, j = idx & 63;
        float s = 0.f;
        const float* ai = A + (size_t)i * D_OUT;
        const float* aj = A + (size_t)j * D_OUT;
        #pragma unroll 8
        for (int d = 0; d < D_OUT; d++) s += ai[d] * aj[d];
        Gs[i][j] = s;
        Ks[i][j] = (i == j) ? 1.f : 0.f;
    }
    __syncthreads();

    for (int k = 0; k < 64; k++) {
        float pinv = 1.f / Gs[k][k];
        if (tid < 64) fcol[tid] = Gs[tid][k];
        __syncthreads();
        if (tid < 64) {
            Gs[k][tid] *= pinv;
            Ks[k][tid] *= pinv;
        }
        __syncthreads();
        for (int idx = tid; idx < 64 * 64; idx += 256) {
            int i = idx >> 6, j = idx & 63;
            if (i != k) {
                float f = fcol[i];
                Gs[i][j] -= f * Gs[k][j];
                Ks[i][j] -= f * Ks[k][j];
            }
        }
        __syncthreads();
    }

    for (int idx = tid; idx < 64 * D_OUT; idx += 256) {
        int m = idx >> 8, d = idx & 255;
        float s = 0.f;
        #pragma unroll 8
        for (int j = 0; j < 64; j++) s += Ks[m][j] * A[(size_t)j * D_OUT + d];
        Mop[(size_t)m * D_OUT + d] = s;
    }
}

// ---------------------------------------------------------------------------
// Trunk GEMM (unchanged best): 64x64 tile, double-buffered, reg prefetch.
// ---------------------------------------------------------------------------
__global__ void __launch_bounds__(256) gemm_kernel(const float* __restrict__ X,
                                                   const float* __restrict__ W,
                                                   const float* __restrict__ bias,
                                                   float* __restrict__ C,
                                                   int K, int N, int do_relu) {
    __shared__ float Xs[2][16][68];
    __shared__ float Ws[2][16][64];

    int tid = threadIdx.x;
    int cb = blockIdx.x * 64;
    int rb = blockIdx.y * 64;
    int ty = tid >> 4, tx = tid & 15;

    u64 acc[4][2];
    #pragma unroll
    for (int i = 0; i < 4; i++) { acc[i][0] = 0ull; acc[i][1] = 0ull; }

    int xr = tid >> 2;
    int xc = (tid & 3) * 4;
    int wr = tid >> 4;
    int wc = (tid & 15) * 4;

    const float* Xp = X + (size_t)(rb + xr) * K + xc;
    const float* Wp = W + (size_t)wr * N + cb + wc;

    float4 xv = *(const float4*)(Xp);
    float4 wv = *(const float4*)(Wp);
    Xs[0][xc + 0][xr] = xv.x;
    Xs[0][xc + 1][xr] = xv.y;
    Xs[0][xc + 2][xr] = xv.z;
    Xs[0][xc + 3][xr] = xv.w;
    *(float4*)&Ws[0][wr][wc] = wv;
    __syncthreads();

    int nk = K >> 4;
    for (int ks = 0; ks < nk - 1; ks++) {
        int p = ks & 1;
        xv = *(const float4*)(Xp + (ks + 1) * 16);
        wv = *(const float4*)(Wp + (size_t)(ks + 1) * 16 * N);
        #pragma unroll
        for (int kk = 0; kk < 16; kk++) {
            float4 a4 = *(float4*)&Xs[p][kk][ty * 4];
            ulonglong2 b = *(ulonglong2*)&Ws[p][kk][tx * 4];
            u64 a0 = pack2(a4.x, a4.x);
            u64 a1 = pack2(a4.y, a4.y);
            u64 a2 = pack2(a4.z, a4.z);
            u64 a3 = pack2(a4.w, a4.w);
            acc[0][0] = ffma2(a0, b.x, acc[0][0]); acc[0][1] = ffma2(a0, b.y, acc[0][1]);
            acc[1][0] = ffma2(a1, b.x, acc[1][0]); acc[1][1] = ffma2(a1, b.y, acc[1][1]);
            acc[2][0] = ffma2(a2, b.x, acc[2][0]); acc[2][1] = ffma2(a2, b.y, acc[2][1]);
            acc[3][0] = ffma2(a3, b.x, acc[3][0]); acc[3][1] = ffma2(a3, b.y, acc[3][1]);
        }
        int pn = p ^ 1;
        Xs[pn][xc + 0][xr] = xv.x;
        Xs[pn][xc + 1][xr] = xv.y;
        Xs[pn][xc + 2][xr] = xv.z;
        Xs[pn][xc + 3][xr] = xv.w;
        *(float4*)&Ws[pn][wr][wc] = wv;
        __syncthreads();
    }
    {
        int p = (nk - 1) & 1;
        #pragma unroll
        for (int kk = 0; kk < 16; kk++) {
            float4 a4 = *(float4*)&Xs[p][kk][ty * 4];
            ulonglong2 b = *(ulonglong2*)&Ws[p][kk][tx * 4];
            u64 a0 = pack2(a4.x, a4.x);
            u64 a1 = pack2(a4.y, a4.y);
            u64 a2 = pack2(a4.z, a4.z);
            u64 a3 = pack2(a4.w, a4.w);
            acc[0][0] = ffma2(a0, b.x, acc[0][0]); acc[0][1] = ffma2(a0, b.y, acc[0][1]);
            acc[1][0] = ffma2(a1, b.x, acc[1][0]); acc[1][1] = ffma2(a1, b.y, acc[1][1]);
            acc[2][0] = ffma2(a2, b.x, acc[2][0]); acc[2][1] = ffma2(a2, b.y, acc[2][1]);
            acc[3][0] = ffma2(a3, b.x, acc[3][0]); acc[3][1] = ffma2(a3, b.y, acc[3][1]);
        }
    }

    float4 bv = *(const float4*)(bias + cb + tx * 4);
    #pragma unroll
    for (int i = 0; i < 4; i++) {
        int row = rb + ty * 4 + i;
        float4 o;
        unpack2(acc[i][0], o.x, o.y);
        unpack2(acc[i][1], o.z, o.w);
        o.x += bv.x; o.y += bv.y; o.z += bv.z; o.w += bv.w;
        if (do_relu) {
            o.x = fmaxf(o.x, 0.f); o.y = fmaxf(o.y, 0.f);
            o.z = fmaxf(o.z, 0.f); o.w = fmaxf(o.w, 0.f);
        }
        *(float4*)(C + (size_t)row * N + cb + tx * 4) = o;
    }
}

// ---------------------------------------------------------------------------
// Tensor-core DR solver (bf16x3), v2: 512 threads / 16 warps per CTA,
// split G1 accumulator chains (depth 12 instead of 48).
//
// Work split per warp w (0..15):
//   G1 (g = z A^T):  m-tile mt = w&1 (16 rows), n-tile nt = w>>1 (8 cols of m)
//   G2 (p = rm Mop): both m-tiles, n-tiles j = 2w, 2w+1 (16 cols of d)
// z / t0 / rho0 master copies: fp32 registers in C-fragment layout.
// ---------------------------------------------------------------------------
#define SA_HI 0
#define SA_LO 33792
#define SM_HI 67584
#define SM_LO 104448
#define SZ_HI 141312
#define SZ_LO 158208
#define SR_HI 175104
#define SR_LO 179712
#define SOLVE_SMEM 184320

__device__ __forceinline__ void g2_block(float p[2][2][4],
                                         u32 a2h0, u32 a2h1, u32 a2l0, u32 a2l1,
                                         const u32* b2h, const u32* b2l) {
    #pragma unroll
    for (int m2 = 0; m2 < 2; m2++)
        #pragma unroll
        for (int j = 0; j < 2; j++)
            #pragma unroll
            for (int f = 0; f < 4; f++) p[m2][j][f] = 0.f;

    #pragma unroll
    for (int kk = 0; kk < 4; kk++) {
        u32 arh[2][4], arl[2][4];
        ldsm4(arh[0], a2h0 + kk * 32);
        ldsm4(arh[1], a2h1 + kk * 32);
        ldsm4(arl[0], a2l0 + kk * 32);
        ldsm4(arl[1], a2l1 + kk * 32);
        #pragma unroll
        for (int j = 0; j < 2; j++) {
            u32 bh[2], bl[2];
            ldsm2(bh, b2h[j] + kk * 32);
            ldsm2(bl, b2l[j] + kk * 32);
            #pragma unroll
            for (int m2 = 0; m2 < 2; m2++) {
                mma_bf16(p[m2][j], arh[m2], bh);
                mma_bf16(p[m2][j], arh[m2], bl);
                mma_bf16(p[m2][j], arl[m2], bh);
            }
        }
    }
}

__global__ void __launch_bounds__(512, 1) solve_kernel(
    const float* __restrict__ A, const float* __restrict__ bcon,
    const float* __restrict__ y0g, const float* __restrict__ Mop,
    const int* __restrict__ p_niter, float* __restrict__ out) {
    extern __shared__ char smem[];
    u32 sb = (u32)__cvta_generic_to_shared(smem);

    int tid = threadIdx.x;
    int lane = tid & 31, w = tid >> 5;      // w: 0..15
    int rb = blockIdx.x * 32;
    int qr = lane >> 2, qc = lane & 3;

    // ---------------- cooperative stage & convert ----------------
    for (int i = tid; i < 64 * 128; i += 512) {
        int row = i >> 7, cp = i & 127;
        float2 v = ((const float2*)A)[i];
        u32 hp, lp; split2(v.x, v.y, hp, lp);
        *(u32*)(smem + SA_HI + row * 528 + cp * 4) = hp;
        *(u32*)(smem + SA_LO + row * 528 + cp * 4) = lp;
    }
    for (int i = tid; i < 64 * 128; i += 512) {
        int m = i >> 7, cp = i & 127;
        float2 v = ((const float2*)Mop)[i];
        int d0 = cp * 2;
        u32 hp, lp; split2(v.x, v.y, hp, lp);
        *(unsigned short*)(smem + SM_HI + d0 * 144 + m * 2)       = (unsigned short)(hp & 0xffff);
        *(unsigned short*)(smem + SM_HI + (d0 + 1) * 144 + m * 2) = (unsigned short)(hp >> 16);
        *(unsigned short*)(smem + SM_LO + d0 * 144 + m * 2)       = (unsigned short)(lp & 0xffff);
        *(unsigned short*)(smem + SM_LO + (d0 + 1) * 144 + m * 2) = (unsigned short)(lp >> 16);
    }
    {
        const float2* yb = (const float2*)(y0g + (size_t)rb * D_OUT);
        for (int i = tid; i < 32 * 128; i += 512) {
            int row = i >> 7, cp = i & 127;
            float2 v = yb[i];
            u32 hp, lp; split2(v.x, v.y, hp, lp);
            *(u32*)(smem + SZ_HI + row * 528 + cp * 4) = hp;
            *(u32*)(smem + SZ_LO + row * 528 + cp * 4) = lp;
        }
    }
    {
        const float2* bb = (const float2*)(bcon + (size_t)rb * M_CON);
        for (int i = tid; i < 32 * 32; i += 512) {
            int row = i >> 5, cp = i & 31;
            float2 v = bb[i];
            u32 hp, lp; split2(v.x, v.y, hp, lp);
            *(u32*)(smem + SR_HI + row * 144 + cp * 4) = hp;
            *(u32*)(smem + SR_LO + row * 144 + cp * 4) = lp;
        }
    }
    __syncthreads();

    // ---------------- fragment address bases ----------------
    int l7 = lane & 7, g8 = (lane >> 3) & 1, g16 = (lane >> 4) & 1;
    int lx = lane & 15, lx7 = lx & 7, lx8 = (lx >> 3) & 1;

    // G1: 1 m-tile, 1 n-tile per warp
    int mt = w & 1;
    int nt = w >> 1;                        // 0..7
    u32 a1h = sb + SZ_HI + (u32)((mt * 16 + l7 + g8 * 8) * 528 + g16 * 16);
    u32 a1l = a1h + (SZ_LO - SZ_HI);
    u32 b1h = sb + SA_HI + (u32)((nt * 8 + lx7) * 528 + lx8 * 16);
    u32 b1l = b1h + (SA_LO - SA_HI);

    // G2: 2 m-tiles x 2 n-tiles per warp (n-range [w*16, w*16+16))
    u32 a2h0 = sb + SR_HI + (u32)((0 * 16 + l7 + g8 * 8) * 144 + g16 * 16);
    u32 a2h1 = sb + SR_HI + (u32)((1 * 16 + l7 + g8 * 8) * 144 + g16 * 16);
    u32 a2l0 = a2h0 + (SR_LO - SR_HI);
    u32 a2l1 = a2h1 + (SR_LO - SR_HI);
    u32 b2h[2], b2l[2];
    #pragma unroll
    for (int j = 0; j < 2; j++) {
        b2h[j] = sb + SM_HI + (u32)(((w * 2 + j) * 8 + lx7) * 144 + lx8 * 16);
        b2l[j] = b2h[j] + (SM_LO - SM_HI);
    }

    // ---------------- prologue: c = bcon @ Mop ; t0, z regs ----------------
    float t0r[2][2][4], zf[2][2][4], rho0[4];
    {
        float c[2][2][4];
        g2_block(c, a2h0, a2h1, a2l0, a2l1, b2h, b2l);
        #pragma unroll
        for (int m2 = 0; m2 < 2; m2++) {
            int r0 = rb + m2 * 16 + qr;
            #pragma unroll
            for (int j = 0; j < 2; j++) {
                int col = w * 16 + j * 8 + qc * 2;
                float2 ya = *(const float2*)(y0g + (size_t)r0 * D_OUT + col);
                float2 yb = *(const float2*)(y0g + (size_t)(r0 + 8) * D_OUT + col);
                t0r[m2][j][0] = 0.5f * ya.x + c[m2][j][0];
                t0r[m2][j][1] = 0.5f * ya.y + c[m2][j][1];
                t0r[m2][j][2] = 0.5f * yb.x + c[m2][j][2];
                t0r[m2][j][3] = 0.5f * yb.y + c[m2][j][3];
                zf[m2][j][0] = ya.x; zf[m2][j][1] = ya.y;
                zf[m2][j][2] = yb.x; zf[m2][j][3] = yb.y;
            }
        }
    }
    __syncthreads();   // bcon staging now free for r

    int niter = *p_niter;
    if (niter <= 0) {
        #pragma unroll
        for (int m2 = 0; m2 < 2; m2++) {
            int r0 = rb + m2 * 16 + qr;
            #pragma unroll
            for (int j = 0; j < 2; j++) {
                int col = w * 16 + j * 8 + qc * 2;
                *(float2*)(out + (size_t)r0 * D_OUT + col)       = make_float2(zf[m2][j][0], zf[m2][j][1]);
                *(float2*)(out + (size_t)(r0 + 8) * D_OUT + col) = make_float2(zf[m2][j][2], zf[m2][j][3]);
            }
        }
        return;
    }

    const float zk = 1.0f - OMEGA_F * 0.5f;   // 0.15
    int rrow0 = mt * 16 + qr;
    int rrow1 = rrow0 + 8;
    int rcol  = nt * 8 + qc * 2;

    for (int it = 0; it < niter; it++) {
        // ---------------- G1: g = z A^T (4 independent accumulator sets) ----
        float cgs[4][4];
        #pragma unroll
        for (int s = 0; s < 4; s++)
            #pragma unroll
            for (int f = 0; f < 4; f++) cgs[s][f] = 0.f;

        #pragma unroll
        for (int kk = 0; kk < 16; kk++) {
            u32 azh[4], azl[4], bh[2], bl[2];
            ldsm4(azh, a1h + kk * 32);
            ldsm4(azl, a1l + kk * 32);
            ldsm2(bh, b1h + kk * 32);
            ldsm2(bl, b1l + kk * 32);
            float* cg = cgs[kk & 3];
            mma_bf16(cg, azh, bh);
            mma_bf16(cg, azh, bl);
            mma_bf16(cg, azl, bh);
        }
        #pragma unroll
        for (int f = 0; f < 4; f++)
            cgs[0][f] = (cgs[0][f] + cgs[1][f]) + (cgs[2][f] + cgs[3][f]);

        // ---------------- pw1: rm = -(0.5 g + rho0) -> r staging ----------------
        if (it == 0) {
            #pragma unroll
            for (int f = 0; f < 4; f++) rho0[f] = 0.5f * cgs[0][f];
        }
        {
            float rm0 = -(0.5f * cgs[0][0] + rho0[0]);
            float rm1 = -(0.5f * cgs[0][1] + rho0[1]);
            float rm2 = -(0.5f * cgs[0][2] + rho0[2]);
            float rm3 = -(0.5f * cgs[0][3] + rho0[3]);
            u32 hp, lp;
            split2(rm0, rm1, hp, lp);
            *(u32*)(smem + SR_HI + rrow0 * 144 + rcol * 2) = hp;
            *(u32*)(smem + SR_LO + rrow0 * 144 + rcol * 2) = lp;
            split2(rm2, rm3, hp, lp);
            *(u32*)(smem + SR_HI + rrow1 * 144 + rcol * 2) = hp;
            *(u32*)(smem + SR_LO + rrow1 * 144 + rcol * 2) = lp;
        }
        __syncthreads();

        // ---------------- G2: p = rm Mop ----------------
        float p[2][2][4];
        g2_block(p, a2h0, a2h1, a2l0, a2l1, b2h, b2l);

        // ---------------- pw2: u = t0 + p ; z / out update ----------------
        bool last = (it == niter - 1);
        #pragma unroll
        for (int m2 = 0; m2 < 2; m2++) {
            int row0 = m2 * 16 + qr;
            int row1 = row0 + 8;
            #pragma unroll
            for (int j = 0; j < 2; j++) {
                int col = w * 16 + j * 8 + qc * 2;
                float u0 = t0r[m2][j][0] + p[m2][j][0];
                float u1 = t0r[m2][j][1] + p[m2][j][1];
                float u2 = t0r[m2][j][2] + p[m2][j][2];
                float u3 = t0r[m2][j][3] + p[m2][j][3];
                if (last) {
                    *(float2*)(out + (size_t)(rb + row0) * D_OUT + col) =
                        make_float2(0.5f * zf[m2][j][0] + u0, 0.5f * zf[m2][j][1] + u1);
                    *(float2*)(out + (size_t)(rb + row1) * D_OUT + col) =
                        make_float2(0.5f * zf[m2][j][2] + u2, 0.5f * zf[m2][j][3] + u3);
                } else {
                    zf[m2][j][0] = zk * zf[m2][j][0] + OMEGA_F * fabsf(u0);
                    zf[m2][j][1] = zk * zf[m2][j][1] + OMEGA_F * fabsf(u1);
                    zf[m2][j][2] = zk * zf[m2][j][2] + OMEGA_F * fabsf(u2);
                    zf[m2][j][3] = zk * zf[m2][j][3] + OMEGA_F * fabsf(u3);
                    u32 hp, lp;
                    split2(zf[m2][j][0], zf[m2][j][1], hp, lp);
                    *(u32*)(smem + SZ_HI + row0 * 528 + col * 2) = hp;
                    *(u32*)(smem + SZ_LO + row0 * 528 + col * 2) = lp;
                    split2(zf[m2][j][2], zf[m2][j][3], hp, lp);
                    *(u32*)(smem + SZ_HI + row1 * 528 + col * 2) = hp;
                    *(u32*)(smem + SZ_LO + row1 * 528 + col * 2) = lp;
                }
            }
        }
        __syncthreads();
    }
}

// ---------------------------------------------------------------------------
extern "C" void kernel_launch(void* const* d_in, const int* in_sizes, int n_in,
                              void* d_out, int out_size) {
    const float* x    = (const float*)d_in[0];
    const float* bcon = (const float*)d_in[1];
    const float* A    = (const float*)d_in[2];
    const float* W1   = (const float*)d_in[3];
    const float* b1   = (const float*)d_in[4];
    const float* W2   = (const float*)d_in[5];
    const float* b2   = (const float*)d_in[6];
    const float* W3   = (const float*)d_in[7];
    const float* b3   = (const float*)d_in[8];
    const float* Wout = (const float*)d_in[9];
    const float* bout = (const float*)d_in[10];
    const int*   nit  = (const int*)d_in[11];
    float* out = (float*)d_out;

    float *p_Mop, *p_h1, *p_h2, *p_y0;
    cudaGetSymbolAddress((void**)&p_Mop, g_Mop);
    cudaGetSymbolAddress((void**)&p_h1, g_h1);
    cudaGetSymbolAddress((void**)&p_h2, g_h2);
    cudaGetSymbolAddress((void**)&p_y0, g_y0);

    gemm_kernel<<<dim3(H_DIM / 64, B_ROWS / 64), 256>>>(x,    W1,   b1,   p_h1, D_INF, H_DIM, 1);
    gemm_kernel<<<dim3(H_DIM / 64, B_ROWS / 64), 256>>>(p_h1, W2,   b2,   p_h2, H_DIM, H_DIM, 1);
    gemm_kernel<<<dim3(H_DIM / 64, B_ROWS / 64), 256>>>(p_h2, W3,   b3,   p_h1, H_DIM, H_DIM, 1);
    gemm_kernel<<<dim3(D_OUT / 64, B_ROWS / 64), 256>>>(p_h1, Wout, bout, p_y0, H_DIM, D_OUT, 0);

    setup_kernel<<<1, 256>>>(A, p_Mop);

    cudaFuncSetAttribute(solve_kernel, cudaFuncAttributeMaxDynamicSharedMemorySize, SOLVE_SMEM);
    solve_kernel<<<B_ROWS / 32, 512, SOLVE_SMEM>>>(A, bcon, p_y0, p_Mop, nit, out);
}